// round 1
// baseline (speedup 1.0000x reference)
#include <cuda_runtime.h>

#define B_  4
#define O_  32
#define C_  32
#define HW_ 32
#define P_  5
#define T_  (C_ * 9)      // 288 taps per output channel
#define EPSF 1e-6f

// Scratch (no allocations allowed): precomputed ramp tables + bias
__device__ float4 g_tab[O_ * T_ * 3];   // per (o,t): {inv0..3},{-p*inv 0..3},{dv0..3}
__device__ float  g_v0[O_ * T_];
__device__ float  g_bias[O_];

// ---------------------------------------------------------------------------
// Prep: sort 5 (pos,val) pairs per (o,t) and build clamped-ramp coefficients.
// f(x) = v0 + sum_k dv_k * clamp((x - p_k) * inv_k, 0, 1)
// which is algebraically identical to the reference's segment-select +
// eps-regularized lerp + boundary clamps.
// ---------------------------------------------------------------------------
__global__ void pc_prep(const float* __restrict__ pos, const float* __restrict__ val) {
    int ot = blockIdx.x * blockDim.x + threadIdx.x;
    if (ot >= O_ * T_) return;
    float p[P_], v[P_];
#pragma unroll
    for (int k = 0; k < P_; k++) { p[k] = pos[ot * P_ + k]; v[k] = val[ot * P_ + k]; }
    // Bose-Nelson optimal 9-comparator network for n=5 (register resident)
#define CE(a, b) do { if (p[a] > p[b]) { float t0 = p[a]; p[a] = p[b]; p[b] = t0; \
                                          float t1 = v[a]; v[a] = v[b]; v[b] = t1; } } while (0)
    CE(0,1); CE(3,4); CE(2,4); CE(2,3); CE(1,4); CE(0,3); CE(0,2); CE(1,3); CE(1,2);
#undef CE
    float inv[4], nq[4], dv[4];
#pragma unroll
    for (int k = 0; k < 4; k++) {
        float den = p[k + 1] - p[k] + EPSF;
        inv[k] = 1.0f / den;
        nq[k]  = -p[k] * inv[k];
        dv[k]  = v[k + 1] - v[k];
    }
    g_tab[ot * 3 + 0] = make_float4(inv[0], inv[1], inv[2], inv[3]);
    g_tab[ot * 3 + 1] = make_float4(nq[0],  nq[1],  nq[2],  nq[3]);
    g_tab[ot * 3 + 2] = make_float4(dv[0],  dv[1],  dv[2],  dv[3]);
    g_v0[ot] = v[0];
}

// bias[o] = sum_t v0[o][t]  (one warp per o)
__global__ void pc_bias() {
    int o = blockIdx.x;
    int lane = threadIdx.x;
    float s = 0.0f;
    for (int t = lane; t < T_; t += 32) s += g_v0[o * T_ + t];
#pragma unroll
    for (int off = 16; off > 0; off >>= 1) s += __shfl_down_sync(0xffffffffu, s, off);
    if (lane == 0) g_bias[o] = s;
}

// ---------------------------------------------------------------------------
// Main: block = (b, o, 8-row strip). 64 threads, 4 px/thread (one row group).
// Per-o table in shared (uniform LDS.128 broadcasts). x staged as per-warp
// 6x34 padded tile; row stride 35 => bank = (3*row + col) mod 32, which makes
// the (4 rows x 8 col-groups-of-4) access pattern conflict-free.
// ---------------------------------------------------------------------------
#define TS_ 35   // shared x-tile row stride in floats

__global__ __launch_bounds__(64) void pc_main(const float* __restrict__ x,
                                              float* __restrict__ out) {
    const int blk = blockIdx.x;
    const int quarter = blk & 3;          // which 8-row strip
    const int o = (blk >> 2) & 31;
    const int b = blk >> 7;
    const int y0 = quarter * 8;

    __shared__ float4 s_tab[T_ * 3];      // 13824 B
    __shared__ float  s_x[2][6 * TS_];    // per-warp padded tile, 840 B each

    const int tid = threadIdx.x;
    {
        const float4* gt = g_tab + o * (T_ * 3);
        for (int i = tid; i < T_ * 3; i += 64) s_tab[i] = gt[i];
    }
    __syncthreads();

    const int warp = tid >> 5;
    const int lane = tid & 31;
    const int rl = lane >> 3;             // 0..3 : row within warp's 4-row group
    const int xg = (lane & 7) * 4;        // 0..28: first of this thread's 4 pixels
    const int yout = y0 + warp * 4 + rl;
    const int rowbase = y0 + warp * 4 - 1; // global row of tile row 0

    const float bias = g_bias[o];
    float acc0 = bias, acc1 = bias, acc2 = bias, acc3 = bias;

    const float* xb = x + b * (C_ * HW_ * HW_);
    float* tile = s_x[warp];

#define SEG(XV, ACC, CI, CQ, CD) do {                       \
        float u_ = fmaf((XV), (CI), (CQ));                  \
        u_ = fminf(fmaxf(u_, 0.0f), 1.0f);                  \
        (ACC) = fmaf(u_, (CD), (ACC));                      \
    } while (0)
#define PX4(XV, ACC) do {                                   \
        SEG(XV, ACC, iv.x, nq.x, dv.x);                     \
        SEG(XV, ACC, iv.y, nq.y, dv.y);                     \
        SEG(XV, ACC, iv.z, nq.z, dv.z);                     \
        SEG(XV, ACC, iv.w, nq.w, dv.w);                     \
    } while (0)

    for (int c = 0; c < C_; c++) {
        const float* xc = xb + c * (HW_ * HW_);
        __syncwarp();   // previous iteration's tile reads done before overwrite
#pragma unroll
        for (int rr = 0; rr < 6; rr++) {
            int gy = rowbase + rr;
            bool rowok = (gy >= 0) && (gy < HW_);
            int gx = lane - 1;                               // smem col = lane
            float vv = (rowok && gx >= 0) ? xc[gy * HW_ + gx] : 0.0f;
            tile[rr * TS_ + lane] = vv;
            if (lane < 2) {                                  // smem cols 32,33
                int gx2 = 31 + lane;
                float v2 = (rowok && gx2 < HW_) ? xc[gy * HW_ + gx2] : 0.0f;
                tile[rr * TS_ + 32 + lane] = v2;
            }
        }
        __syncwarp();

        // 3 rows x 6 cols neighborhood for this thread's 4 pixels -> registers
        float vreg[3][6];
#pragma unroll
        for (int ii = 0; ii < 3; ii++)
#pragma unroll
            for (int jj = 0; jj < 6; jj++)
                vreg[ii][jj] = tile[(rl + ii) * TS_ + xg + jj];

        const float4* tp = s_tab + c * 27;
#pragma unroll
        for (int i = 0; i < 3; i++) {
#pragma unroll
            for (int j = 0; j < 3; j++) {
                float4 iv = tp[(i * 3 + j) * 3 + 0];   // uniform addr -> broadcast
                float4 nq = tp[(i * 3 + j) * 3 + 1];
                float4 dv = tp[(i * 3 + j) * 3 + 2];
                PX4(vreg[i][j + 0], acc0);
                PX4(vreg[i][j + 1], acc1);
                PX4(vreg[i][j + 2], acc2);
                PX4(vreg[i][j + 3], acc3);
            }
        }
    }
#undef PX4
#undef SEG

    float4 res = make_float4(acc0, acc1, acc2, acc3);
    int oidx = ((b * O_ + o) * HW_ + yout) * HW_ + xg;   // xg % 4 == 0 -> 16B aligned
    *reinterpret_cast<float4*>(out + oidx) = res;
}

extern "C" void kernel_launch(void* const* d_in, const int* in_sizes, int n_in,
                              void* d_out, int out_size) {
    const float* x   = (const float*)d_in[0];
    const float* pos = (const float*)d_in[1];
    const float* val = (const float*)d_in[2];
    float* out = (float*)d_out;

    pc_prep<<<(O_ * T_ + 127) / 128, 128>>>(pos, val);
    pc_bias<<<O_, 32>>>();
    pc_main<<<B_ * O_ * 4, 64>>>(x, out);
}

// round 2
// speedup vs baseline: 2.1231x; 2.1231x over previous
#include <cuda_runtime.h>

#define B_  4
#define O_  32
#define C_  32
#define HW_ 32
#define P_  5
#define T_  (C_ * 9)      // 288 taps per output channel
#define EPSF 1e-6f
#define TS_ 35            // shared x-tile row stride (floats): bank = (3*row+col)%32

// ---------------------------------------------------------------------------
// Single fused kernel.
// Grid: 512 blocks = (b, o, 8-row strip). Block: 256 threads = 8 warps.
//
// Phase 0 (per block): sort this o's 288 (pos,val)[5] tables (Bose-Nelson 9-CE,
//   register resident) and build clamped-ramp coefficients in shared:
//     f(x) = v0 + sum_k dv_k * clamp((x - p_k)*inv_k, 0, 1)
//   (algebraically identical to the reference's eps-lerp + boundary clamps).
//   Bias = sum_t v0 via one warp reduction.
//
// Phase 1: 4 warp-pairs x 8 channels each. Within a pair, each warp covers a
//   4-row group at 4 px/thread. x staged per-warp as a 6x34 padded tile
//   (stride 35 -> conflict-free for the 4-row x 8-colgroup pattern), only
//   __syncwarp needed. Table reads are uniform-address LDS.128 broadcasts.
//
// Phase 2: float4 smem reduction across the 4 pairs + bias, STG.128.
// ---------------------------------------------------------------------------
__global__ __launch_bounds__(256) void pc_fused(const float* __restrict__ x,
                                                const float* __restrict__ pos,
                                                const float* __restrict__ val,
                                                float* __restrict__ out) {
    const int blk = blockIdx.x;
    const int quarter = blk & 3;          // which 8-row strip
    const int o = (blk >> 2) & 31;
    const int b = blk >> 7;
    const int y0 = quarter * 8;

    __shared__ float4 s_tab[T_ * 3];      // 13824 B: per t {inv4},{-p*inv 4},{dv4}
    __shared__ float  s_v0[T_];           // 1152 B
    __shared__ float  s_x[8][6 * TS_];    // per-warp padded tiles
    __shared__ float4 s_red[4][64];       // cross-pair reduction
    __shared__ float  s_bias;

    const int tid = threadIdx.x;

    // ---- Phase 0: build tables for this o ----
    const float* pbase = pos + o * (T_ * P_);
    const float* vbase = val + o * (T_ * P_);
#pragma unroll
    for (int rep = 0; rep < 2; rep++) {
        int ot = tid + rep * 256;
        if (ot < T_) {
            float p[P_], v[P_];
#pragma unroll
            for (int k = 0; k < P_; k++) { p[k] = pbase[ot * P_ + k]; v[k] = vbase[ot * P_ + k]; }
#define CE(a, bb) do { if (p[a] > p[bb]) { float t0 = p[a]; p[a] = p[bb]; p[bb] = t0; \
                                           float t1 = v[a]; v[a] = v[bb]; v[bb] = t1; } } while (0)
            CE(0,1); CE(3,4); CE(2,4); CE(2,3); CE(1,4); CE(0,3); CE(0,2); CE(1,3); CE(1,2);
#undef CE
            float inv[4], nq[4], dv[4];
#pragma unroll
            for (int k = 0; k < 4; k++) {
                float den = p[k + 1] - p[k] + EPSF;
                inv[k] = 1.0f / den;
                nq[k]  = -p[k] * inv[k];
                dv[k]  = v[k + 1] - v[k];
            }
            s_tab[ot * 3 + 0] = make_float4(inv[0], inv[1], inv[2], inv[3]);
            s_tab[ot * 3 + 1] = make_float4(nq[0],  nq[1],  nq[2],  nq[3]);
            s_tab[ot * 3 + 2] = make_float4(dv[0],  dv[1],  dv[2],  dv[3]);
            s_v0[ot] = v[0];
        }
    }
    __syncthreads();

    if (tid < 32) {       // warp 0: bias = sum_t v0
        float s = 0.0f;
#pragma unroll
        for (int k = 0; k < 9; k++) s += s_v0[tid + k * 32];
#pragma unroll
        for (int off = 16; off > 0; off >>= 1) s += __shfl_down_sync(0xffffffffu, s, off);
        if (tid == 0) s_bias = s;
    }
    __syncthreads();

    // ---- Phase 1: main accumulation ----
    const int warp = tid >> 5;
    const int lane = tid & 31;
    const int pair = warp >> 1;           // 0..3 : which 8-channel group
    const int wp   = warp & 1;            // 0/1  : which 4-row group of the strip
    const int rl = lane >> 3;             // 0..3 : row within 4-row group
    const int xg = (lane & 7) * 4;        // 0..28: first of this thread's 4 px
    const int rowbase = y0 + wp * 4 - 1;  // global row of tile row 0

    float acc0 = 0.0f, acc1 = 0.0f, acc2 = 0.0f, acc3 = 0.0f;

    const float* xb = x + b * (C_ * HW_ * HW_);
    float* tile = s_x[warp];
    const int cBase = pair * 8;

#define SEG(XV, ACC, CI, CQ, CD) do {                       \
        float u_ = fmaf((XV), (CI), (CQ));                  \
        u_ = fminf(fmaxf(u_, 0.0f), 1.0f);                  \
        (ACC) = fmaf(u_, (CD), (ACC));                      \
    } while (0)
#define PX4(XV, ACC) do {                                   \
        SEG(XV, ACC, iv.x, nq.x, dv.x);                     \
        SEG(XV, ACC, iv.y, nq.y, dv.y);                     \
        SEG(XV, ACC, iv.z, nq.z, dv.z);                     \
        SEG(XV, ACC, iv.w, nq.w, dv.w);                     \
    } while (0)

    for (int cc = 0; cc < 8; cc++) {
        const int c = cBase + cc;
        const float* xc = xb + c * (HW_ * HW_);
        __syncwarp();   // previous iteration's tile reads done before overwrite
#pragma unroll
        for (int rr = 0; rr < 6; rr++) {
            int gy = rowbase + rr;
            bool rowok = (gy >= 0) && (gy < HW_);
            int gx = lane - 1;                               // smem col = lane
            float vv = (rowok && gx >= 0) ? xc[gy * HW_ + gx] : 0.0f;
            tile[rr * TS_ + lane] = vv;
            if (lane < 2) {                                  // smem cols 32,33
                int gx2 = 31 + lane;
                float v2 = (rowok && gx2 < HW_) ? xc[gy * HW_ + gx2] : 0.0f;
                tile[rr * TS_ + 32 + lane] = v2;
            }
        }
        __syncwarp();

        // 3 rows x 6 cols neighborhood for this thread's 4 px -> registers
        float vreg[3][6];
#pragma unroll
        for (int ii = 0; ii < 3; ii++)
#pragma unroll
            for (int jj = 0; jj < 6; jj++)
                vreg[ii][jj] = tile[(rl + ii) * TS_ + xg + jj];

        const float4* tp = s_tab + c * 27;
#pragma unroll
        for (int i = 0; i < 3; i++) {
#pragma unroll
            for (int j = 0; j < 3; j++) {
                float4 iv = tp[(i * 3 + j) * 3 + 0];   // uniform addr -> broadcast
                float4 nq = tp[(i * 3 + j) * 3 + 1];
                float4 dv = tp[(i * 3 + j) * 3 + 2];
                PX4(vreg[i][j + 0], acc0);
                PX4(vreg[i][j + 1], acc1);
                PX4(vreg[i][j + 2], acc2);
                PX4(vreg[i][j + 3], acc3);
            }
        }
    }
#undef PX4
#undef SEG

    // ---- Phase 2: reduce across the 4 pairs ----
    // pixel-group id g = row*8 + colgroup, row = wp*4+rl, colgroup = lane&7
    const int g = wp * 32 + rl * 8 + (lane & 7);
    s_red[pair][g] = make_float4(acc0, acc1, acc2, acc3);
    __syncthreads();

    if (tid < 64) {
        float4 r0 = s_red[0][tid];
        float4 r1 = s_red[1][tid];
        float4 r2 = s_red[2][tid];
        float4 r3 = s_red[3][tid];
        float bias = s_bias;
        float4 res;
        res.x = bias + (r0.x + r1.x) + (r2.x + r3.x);
        res.y = bias + (r0.y + r1.y) + (r2.y + r3.y);
        res.z = bias + (r0.z + r1.z) + (r2.z + r3.z);
        res.w = bias + (r0.w + r1.w) + (r2.w + r3.w);
        int row = tid >> 3;
        int col0 = (tid & 7) * 4;
        int oidx = ((b * O_ + o) * HW_ + y0 + row) * HW_ + col0;  // 16B aligned
        *reinterpret_cast<float4*>(out + oidx) = res;
    }
}

extern "C" void kernel_launch(void* const* d_in, const int* in_sizes, int n_in,
                              void* d_out, int out_size) {
    const float* x   = (const float*)d_in[0];
    const float* pos = (const float*)d_in[1];
    const float* val = (const float*)d_in[2];
    float* out = (float*)d_out;

    pc_fused<<<B_ * O_ * 4, 256>>>(x, pos, val, out);
}

// round 3
// speedup vs baseline: 2.2971x; 1.0820x over previous
#include <cuda_runtime.h>

#define B_  4
#define O_  32
#define C_  32
#define HW_ 32
#define P_  5
#define T_  (C_ * 9)      // 288 taps per output channel
#define EPSF 1e-6f
#define TS_ 35            // x-tile row stride (floats): bank = (3*row+col)%32

// FFMA with .sat: result clamped to [0,1]. Identical to
// fminf(fmaxf(fmaf(a,b,c),0.f),1.f) for non-NaN results (ours are finite).
__device__ __forceinline__ float fma_sat(float a, float b, float c) {
    float d;
    asm("fma.rn.sat.f32 %0, %1, %2, %3;" : "=f"(d) : "f"(a), "f"(b), "f"(c));
    return d;
}

// ---------------------------------------------------------------------------
// Single fused kernel. Grid: 512 = (b, o, 8-row strip). Block: 256 = 8 warps.
// Phase 0: per-block sort of this o's 288 (pos,val)[5] tables (Bose-Nelson 9
//   comparators, registers) -> clamped-ramp coefficients in shared:
//     f(x) = v0 + sum_k dv_k * sat((x - p_k)*inv_k)
// Phase 1: 4 warp-pairs x 8 channels each; per warp 4-row group, 4 px/thread.
//   x staged per-warp in DOUBLE-BUFFERED 6x34 padded tiles (prefetch next
//   channel while computing current). Table reads = uniform LDS.128 broadcast.
// Phase 2: float4 smem reduction across pairs + bias, STG.128.
// ---------------------------------------------------------------------------
__global__ __launch_bounds__(256, 4) void pc_fused(const float* __restrict__ x,
                                                   const float* __restrict__ pos,
                                                   const float* __restrict__ val,
                                                   float* __restrict__ out) {
    const int blk = blockIdx.x;
    const int quarter = blk & 3;
    const int o = (blk >> 2) & 31;
    const int b = blk >> 7;
    const int y0 = quarter * 8;

    __shared__ float4 s_tab[T_ * 3];        // 13824 B
    __shared__ float  s_v0[T_];             // 1152 B
    __shared__ float  s_x[16][6 * TS_];     // 2 tiles per warp, 13440 B
    __shared__ float4 s_red[4][64];         // 4096 B
    __shared__ float  s_bias;

    const int tid = threadIdx.x;

    // ---- Phase 0: build coefficient tables for this o ----
    const float* pbase = pos + o * (T_ * P_);
    const float* vbase = val + o * (T_ * P_);
#pragma unroll
    for (int rep = 0; rep < 2; rep++) {
        int ot = tid + rep * 256;
        if (ot < T_) {
            float p[P_], v[P_];
#pragma unroll
            for (int k = 0; k < P_; k++) { p[k] = pbase[ot * P_ + k]; v[k] = vbase[ot * P_ + k]; }
#define CE(a, bb) do { if (p[a] > p[bb]) { float t0 = p[a]; p[a] = p[bb]; p[bb] = t0; \
                                           float t1 = v[a]; v[a] = v[bb]; v[bb] = t1; } } while (0)
            CE(0,1); CE(3,4); CE(2,4); CE(2,3); CE(1,4); CE(0,3); CE(0,2); CE(1,3); CE(1,2);
#undef CE
            float inv[4], nq[4], dv[4];
#pragma unroll
            for (int k = 0; k < 4; k++) {
                float den = p[k + 1] - p[k] + EPSF;
                inv[k] = 1.0f / den;
                nq[k]  = -p[k] * inv[k];
                dv[k]  = v[k + 1] - v[k];
            }
            s_tab[ot * 3 + 0] = make_float4(inv[0], inv[1], inv[2], inv[3]);
            s_tab[ot * 3 + 1] = make_float4(nq[0],  nq[1],  nq[2],  nq[3]);
            s_tab[ot * 3 + 2] = make_float4(dv[0],  dv[1],  dv[2],  dv[3]);
            s_v0[ot] = v[0];
        }
    }
    __syncthreads();

    if (tid < 32) {
        float s = 0.0f;
#pragma unroll
        for (int k = 0; k < 9; k++) s += s_v0[tid + k * 32];
#pragma unroll
        for (int off = 16; off > 0; off >>= 1) s += __shfl_down_sync(0xffffffffu, s, off);
        if (tid == 0) s_bias = s;
    }
    __syncthreads();

    // ---- Phase 1 ----
    const int warp = tid >> 5;
    const int lane = tid & 31;
    const int pair = warp >> 1;            // 0..3: 8-channel group
    const int wp   = warp & 1;             // 0/1 : 4-row group within strip
    const int rl   = lane >> 3;            // 0..3: row within 4-row group
    const int xg   = (lane & 7) * 4;       // 0,4,...,28
    const int rowbase = y0 + wp * 4 - 1;

    // Per-row fill constants (channel-invariant)
    int  rowoff[6];
    bool okA[6], okB[6];
#pragma unroll
    for (int rr = 0; rr < 6; rr++) {
        int gy = rowbase + rr;
        bool rowok = (gy >= 0) && (gy < HW_);
        rowoff[rr] = gy * HW_;
        okA[rr] = rowok && (lane >= 1);    // main col: gx = lane-1
        okB[rr] = rowok && (lane == 0);    // extra col 32: gx = 31 (lane 1 -> 0)
    }

    float acc0 = 0.0f, acc1 = 0.0f, acc2 = 0.0f, acc3 = 0.0f;

    const float* xb = x + b * (C_ * HW_ * HW_);
    const int cBase = pair * 8;
    const float* xc = xb + cBase * (HW_ * HW_);
    float* tA = s_x[warp * 2];
    float* tB = s_x[warp * 2 + 1];

#define FILL(T_PTR, XC) do {                                               \
    const float* xp_ = (XC);                                               \
    _Pragma("unroll")                                                      \
    for (int rr = 0; rr < 6; rr++) {                                       \
        float v_ = okA[rr] ? xp_[rowoff[rr] + lane - 1] : 0.0f;            \
        (T_PTR)[rr * TS_ + lane] = v_;                                     \
        if (lane < 2) {                                                    \
            float v2_ = okB[rr] ? xp_[rowoff[rr] + 31] : 0.0f;             \
            (T_PTR)[rr * TS_ + 32 + lane] = v2_;                           \
        }                                                                  \
    } } while (0)

#define SEG(XV, ACC, CI, CQ, CD) do {                                      \
        float u_ = fma_sat((XV), (CI), (CQ));                              \
        (ACC) = fmaf(u_, (CD), (ACC));                                     \
    } while (0)
#define PX4(XV, ACC) do {                                                  \
        SEG(XV, ACC, iv.x, nq.x, dv.x);                                    \
        SEG(XV, ACC, iv.y, nq.y, dv.y);                                    \
        SEG(XV, ACC, iv.z, nq.z, dv.z);                                    \
        SEG(XV, ACC, iv.w, nq.w, dv.w);                                    \
    } while (0)

    FILL(tA, xc);                          // prefetch channel cBase+0

    for (int cc = 0; cc < 8; cc++) {
        float* cur = (cc & 1) ? tB : tA;
        float* nxt = (cc & 1) ? tA : tB;
        __syncwarp();                      // prev fill visible / prev reads done

        // neighborhood -> registers
        float vreg[3][6];
#pragma unroll
        for (int ii = 0; ii < 3; ii++)
#pragma unroll
            for (int jj = 0; jj < 6; jj++)
                vreg[ii][jj] = cur[(rl + ii) * TS_ + xg + jj];

        if (cc < 7) FILL(nxt, xc + (HW_ * HW_));   // overlap LDG with math
        xc += HW_ * HW_;

        const float4* tp = s_tab + (cBase + cc) * 27;
#pragma unroll
        for (int i = 0; i < 3; i++) {
#pragma unroll
            for (int j = 0; j < 3; j++) {
                float4 iv = tp[(i * 3 + j) * 3 + 0];   // uniform -> broadcast
                float4 nq = tp[(i * 3 + j) * 3 + 1];
                float4 dv = tp[(i * 3 + j) * 3 + 2];
                PX4(vreg[i][j + 0], acc0);
                PX4(vreg[i][j + 1], acc1);
                PX4(vreg[i][j + 2], acc2);
                PX4(vreg[i][j + 3], acc3);
            }
        }
    }
#undef PX4
#undef SEG
#undef FILL

    // ---- Phase 2: reduce across the 4 pairs ----
    const int g = wp * 32 + rl * 8 + (lane & 7);
    s_red[pair][g] = make_float4(acc0, acc1, acc2, acc3);
    __syncthreads();

    if (tid < 64) {
        float4 r0 = s_red[0][tid];
        float4 r1 = s_red[1][tid];
        float4 r2 = s_red[2][tid];
        float4 r3 = s_red[3][tid];
        float bias = s_bias;
        float4 res;
        res.x = bias + (r0.x + r1.x) + (r2.x + r3.x);
        res.y = bias + (r0.y + r1.y) + (r2.y + r3.y);
        res.z = bias + (r0.z + r1.z) + (r2.z + r3.z);
        res.w = bias + (r0.w + r1.w) + (r2.w + r3.w);
        int row = tid >> 3;
        int col0 = (tid & 7) * 4;
        int oidx = ((b * O_ + o) * HW_ + y0 + row) * HW_ + col0;
        *reinterpret_cast<float4*>(out + oidx) = res;
    }
}

extern "C" void kernel_launch(void* const* d_in, const int* in_sizes, int n_in,
                              void* d_out, int out_size) {
    const float* x   = (const float*)d_in[0];
    const float* pos = (const float*)d_in[1];
    const float* val = (const float*)d_in[2];
    float* out = (float*)d_out;

    pc_fused<<<B_ * O_ * 4, 256>>>(x, pos, val, out);
}